// round 5
// baseline (speedup 1.0000x reference)
#include <cuda_runtime.h>
#include <math.h>

#define B_   4
#define SEQ  2048
#define DM   256
#define NH   4
#define DH   64
#define BHT  16       // B_*NH

typedef unsigned long long ull;

// packed fp32x2 ops (FFMA2 path — SASS_QUICKREF: only reachable via PTX)
#define FMA2(d, a, b) asm("fma.rn.f32x2 %0, %1, %2, %0;" : "+l"(d) : "l"(a), "l"(b))
#define MUL2(d, a, b) asm("mul.rn.f32x2 %0, %1, %2;" : "=l"(d) : "l"(a), "l"(b))
__device__ __forceinline__ ull pack2(float lo, float hi) {
    ull r; asm("mov.b64 %0, {%1, %2};" : "=l"(r) : "f"(lo), "f"(hi)); return r;
}
__device__ __forceinline__ float2 unpack2(ull v) {
    float2 r; asm("mov.b64 {%0, %1}, %2;" : "=f"(r.x), "=f"(r.y) : "l"(v)); return r;
}

// ---------------- scratch (device globals; no allocation) ----------------
__device__ float g_Q [BHT * SEQ * DH];   // [bh][s][64]  (pre-scaled by 1/8)
__device__ float g_K [BHT * SEQ * DH];   // effective K = K·G^T
__device__ float g_V [BHT * SEQ * DH];
__device__ float g_O [B_  * SEQ * DM];   // attn output
__device__ float g_Wk[DM * DM];          // folded Wk_eff
__device__ float g_bk[DM];               // folded bk_eff

// =====================================================================
// Kernel 0: prep — fold TT interaction into Wk.
//   M_h[d,e] = sum_{a,r} W2[h,d,a,r] * W2[h,a,e,r];  G = I + (alpha/64) M
// =====================================================================
#define PREP_SMEM ((64 * 256 + 64 * 65) * 4)

__global__ __launch_bounds__(256) void prep_kernel(const float* __restrict__ W2,
                                                   const float* __restrict__ alpha_p,
                                                   const float* __restrict__ Wk,
                                                   const float* __restrict__ bk)
{
    extern __shared__ float sm[];
    float* Ws = sm;              // 64 x 256
    float* Gs = sm + 64 * 256;   // 64 x 65
    const int h = blockIdx.x;
    const int tid = threadIdx.x;
    const float* W2h = W2 + (size_t)h * 64 * 256;

    for (int idx = tid; idx < 64 * 256; idx += 256) Ws[idx] = W2h[idx];
    __syncthreads();

    const float c = alpha_p[0] * (1.0f / 64.0f);
    for (int idx = tid; idx < 64 * 64; idx += 256) {
        int d = idx >> 6, e = idx & 63;
        float s = 0.f;
        #pragma unroll 8
        for (int a = 0; a < 64; a++) {
            float4 wa = *(const float4*)&Ws[d * 256 + a * 4];
            float4 wb = *(const float4*)&Ws[a * 256 + e * 4];
            s += wa.x * wb.x + wa.y * wb.y + wa.z * wb.z + wa.w * wb.w;
        }
        Gs[d * 65 + e] = c * s + ((d == e) ? 1.0f : 0.0f);
    }
    __syncthreads();

    {
        const int cr = tid;
        float kin[64];
        #pragma unroll
        for (int e = 0; e < 64; e++) kin[e] = Wk[(size_t)cr * DM + h * 64 + e];
        for (int d = 0; d < 64; d++) {
            float s = 0.f;
            #pragma unroll
            for (int e = 0; e < 64; e++) s += kin[e] * Gs[d * 65 + e];
            g_Wk[(size_t)cr * DM + h * 64 + d] = s;
        }
    }
    if (tid < 64) {
        int d = tid;
        float s = 0.f;
        #pragma unroll
        for (int e = 0; e < 64; e++) s += bk[h * 64 + e] * Gs[d * 65 + e];
        g_bk[h * 64 + d] = s;
    }
}

// =====================================================================
// Kernel 1: QKV projection GEMM (f32x2).  z=0:Q(x1/8)  z=1:K(folded)  z=2:V
// As: 64x20 (k contiguous, even stride).  Bst: transposed 64x18 [n][k].
// Column ownership cyclic (n = tx + 16*jj) -> conflict-free 8B b2 reads.
// =====================================================================
__global__ __launch_bounds__(256) void proj_kernel(
    const float* __restrict__ Xq, const float* __restrict__ Xk, const float* __restrict__ Xv,
    const float* __restrict__ Wq, const float* __restrict__ bq,
    const float* __restrict__ Wv, const float* __restrict__ bv)
{
    __shared__ float As[64 * 20];
    __shared__ float Bst[64 * 18];
    const int z = blockIdx.z;
    const float* X    = (z == 0) ? Xq : (z == 1) ? Xk : Xv;
    const float* W    = (z == 0) ? Wq : (z == 1) ? g_Wk : Wv;
    const float* bias = (z == 0) ? bq : (z == 1) ? g_bk : bv;
    const int m0 = blockIdx.x * 64;
    const int n0 = blockIdx.y * 64;
    const int tid = threadIdx.x;
    const int tx = tid & 15, ty = tid >> 4;

    ull acc2[4][4] = {};
    for (int k0 = 0; k0 < DM; k0 += 16) {
        {
            int i = tid >> 2, c = tid & 3;
            float4 a = *(const float4*)&X[(size_t)(m0 + i) * DM + k0 + c * 4];
            *(float4*)&As[i * 20 + c * 4] = a;
            int kk = tid >> 4, c2 = tid & 15;
            float4 w = *(const float4*)&W[(size_t)(k0 + kk) * DM + n0 + c2 * 4];
            Bst[(c2 * 4 + 0) * 18 + kk] = w.x;
            Bst[(c2 * 4 + 1) * 18 + kk] = w.y;
            Bst[(c2 * 4 + 2) * 18 + kk] = w.z;
            Bst[(c2 * 4 + 3) * 18 + kk] = w.w;
        }
        __syncthreads();
        #pragma unroll
        for (int p = 0; p < 8; p++) {
            ull a2[4], b2[4];
            #pragma unroll
            for (int ii = 0; ii < 4; ii++) a2[ii] = *(const ull*)&As[(ty * 4 + ii) * 20 + 2 * p];
            #pragma unroll
            for (int jj = 0; jj < 4; jj++) b2[jj] = *(const ull*)&Bst[(tx + 16 * jj) * 18 + 2 * p];
            #pragma unroll
            for (int ii = 0; ii < 4; ii++)
                #pragma unroll
                for (int jj = 0; jj < 4; jj++)
                    FMA2(acc2[ii][jj], a2[ii], b2[jj]);
        }
        __syncthreads();
    }

    const int h = n0 >> 6;
    float* dst = (z == 0) ? g_Q : (z == 1) ? g_K : g_V;
    const float sc = (z == 0) ? 0.125f : 1.0f;
    #pragma unroll
    for (int ii = 0; ii < 4; ii++) {
        int m = m0 + ty * 4 + ii;
        int b = m >> 11, s = m & (SEQ - 1);
        size_t base = (size_t)((b * NH + h) * SEQ + s) * DH;
        #pragma unroll
        for (int jj = 0; jj < 4; jj++) {
            int col = tx + 16 * jj;
            float2 v = unpack2(acc2[ii][jj]);
            dst[base + col] = (v.x + v.y + bias[n0 + col]) * sc;
        }
    }
}

// =====================================================================
// Kernel 2: flash attention, d=64, f32x2 packed FMA throughout.
// Qs/Ks/Vt: 64x64 XOR-swizzled tiles (Vt holds V transposed [d][k]).
// Ps: 64x68.  16x16 threads, 4x4 register tiles, packed accumulators.
// =====================================================================
#define ATTN_SMEM ((3 * 64 * 64 + 64 * 68) * 4)   // 66,560 B

__device__ __forceinline__ int swz64(int row, int c4) {
    int cs = (c4 & 8) | ((c4 ^ (row >> 2)) & 7);
    return row * 64 + (cs << 2);
}

__global__ __launch_bounds__(256, 2) void attn_kernel()
{
    extern __shared__ float sm[];
    float* Qs = sm;                       // 64*64 swizzled [q][d]
    float* Ks = sm + 64 * 64;             // 64*64 swizzled [k][d]
    float* Vt = sm + 2 * 64 * 64;         // 64*64 swizzled [d][k]  (transposed V)
    float* Ps = sm + 3 * 64 * 64;         // 64*68        [q][k]
    const int bh = blockIdx.y;
    const int qt = blockIdx.x;
    const int tid = threadIdx.x;
    const int tx = tid & 15, ty = tid >> 4;

    const float* Qg = g_Q + (size_t)(bh * SEQ + qt * 64) * DH;
    #pragma unroll
    for (int it = 0; it < 4; it++) {
        int idx = tid + it * 256;
        int i = idx >> 4, c = idx & 15;
        *(float4*)&Qs[swz64(i, c)] = *(const float4*)&Qg[i * DH + c * 4];
    }

    float m_i[4], l_i[4];
    ull o2[4][4] = {};
    #pragma unroll
    for (int ii = 0; ii < 4; ii++) { m_i[ii] = -1e30f; l_i[ii] = 0.f; }
    __syncthreads();

    for (int kt = 0; kt < 32; kt++) {
        const float* Kg = g_K + (size_t)(bh * SEQ + kt * 64) * DH;
        const float* Vg = g_V + (size_t)(bh * SEQ + kt * 64) * DH;
        #pragma unroll
        for (int it = 0; it < 4; it++) {
            int idx = tid + it * 256;
            int i = idx >> 4, c = idx & 15;     // i = k-row, c = d-chunk
            *(float4*)&Ks[swz64(i, c)] = *(const float4*)&Kg[i * DH + c * 4];
            // V transpose: Vt[d][k] with d = c*4+u, k = i (swizzled chunks along k)
            float4 vv = *(const float4*)&Vg[i * DH + c * 4];
            int ch = i >> 2, k3 = i & 3;
            int scz = ((ch & 8) | ((ch ^ c) & 7)) << 2;
            float vvv[4] = {vv.x, vv.y, vv.z, vv.w};
            #pragma unroll
            for (int u = 0; u < 4; u++)
                Vt[(c * 4 + u) * 64 + scz + k3] = vvv[u];
        }
        __syncthreads();

        // ---- S = Q . K^T  (packed over d) ----
        ull s2[4][4] = {};
        #pragma unroll 4
        for (int c4 = 0; c4 < 16; c4++) {
            ull ql[4], qh[4], kl[4], kh[4];
            #pragma unroll
            for (int ii = 0; ii < 4; ii++) {
                int off = swz64(ty * 4 + ii, c4);
                ql[ii] = *(const ull*)&Qs[off];
                qh[ii] = *(const ull*)&Qs[off + 2];
            }
            #pragma unroll
            for (int jj = 0; jj < 4; jj++) {
                int off = swz64(tx * 4 + jj, c4);
                kl[jj] = *(const ull*)&Ks[off];
                kh[jj] = *(const ull*)&Ks[off + 2];
            }
            #pragma unroll
            for (int ii = 0; ii < 4; ii++)
                #pragma unroll
                for (int jj = 0; jj < 4; jj++) {
                    FMA2(s2[ii][jj], ql[ii], kl[jj]);
                    FMA2(s2[ii][jj], qh[ii], kh[jj]);
                }
        }

        // ---- online softmax ----
        #pragma unroll
        for (int ii = 0; ii < 4; ii++) {
            float s[4];
            #pragma unroll
            for (int jj = 0; jj < 4; jj++) {
                float2 v = unpack2(s2[ii][jj]);
                s[jj] = v.x + v.y;
            }
            float r = fmaxf(fmaxf(s[0], s[1]), fmaxf(s[2], s[3]));
            r = fmaxf(r, __shfl_xor_sync(0xffffffffu, r, 1));
            r = fmaxf(r, __shfl_xor_sync(0xffffffffu, r, 2));
            r = fmaxf(r, __shfl_xor_sync(0xffffffffu, r, 4));
            r = fmaxf(r, __shfl_xor_sync(0xffffffffu, r, 8));
            float mn = fmaxf(m_i[ii], r);
            float corr = __expf(m_i[ii] - mn);
            m_i[ii] = mn;
            float rs = 0.f;
            #pragma unroll
            for (int jj = 0; jj < 4; jj++) {
                float p = __expf(s[jj] - mn);
                s[jj] = p;
                rs += p;
            }
            rs += __shfl_xor_sync(0xffffffffu, rs, 1);
            rs += __shfl_xor_sync(0xffffffffu, rs, 2);
            rs += __shfl_xor_sync(0xffffffffu, rs, 4);
            rs += __shfl_xor_sync(0xffffffffu, rs, 8);
            l_i[ii] = l_i[ii] * corr + rs;
            ull c2 = pack2(corr, corr);
            #pragma unroll
            for (int jj = 0; jj < 4; jj++) MUL2(o2[ii][jj], o2[ii][jj], c2);
            *(float4*)&Ps[(ty * 4 + ii) * 68 + tx * 4] =
                make_float4(s[0], s[1], s[2], s[3]);
        }
        __syncthreads();

        // ---- O += P @ V  (packed over k; V read transposed) ----
        #pragma unroll 4
        for (int kg = 0; kg < 16; kg++) {
            ull pl[4], ph[4], vl[4], vh[4];
            #pragma unroll
            for (int ii = 0; ii < 4; ii++) {
                int off = (ty * 4 + ii) * 68 + kg * 4;
                pl[ii] = *(const ull*)&Ps[off];
                ph[ii] = *(const ull*)&Ps[off + 2];
            }
            #pragma unroll
            for (int jj = 0; jj < 4; jj++) {
                int off = swz64(tx * 4 + jj, kg);
                vl[jj] = *(const ull*)&Vt[off];
                vh[jj] = *(const ull*)&Vt[off + 2];
            }
            #pragma unroll
            for (int ii = 0; ii < 4; ii++)
                #pragma unroll
                for (int jj = 0; jj < 4; jj++) {
                    FMA2(o2[ii][jj], pl[ii], vl[jj]);
                    FMA2(o2[ii][jj], ph[ii], vh[jj]);
                }
        }
        __syncthreads();
    }

    const int b = bh >> 2, h = bh & 3;
    #pragma unroll
    for (int ii = 0; ii < 4; ii++) {
        float inv = 1.0f / l_i[ii];
        int srow = qt * 64 + ty * 4 + ii;
        size_t base = (size_t)(b * SEQ + srow) * DM + h * 64;
        #pragma unroll
        for (int jj = 0; jj < 4; jj++) {
            float2 v = unpack2(o2[ii][jj]);
            g_O[base + tx * 4 + jj] = (v.x + v.y) * inv;
        }
    }
}

// =====================================================================
// Kernel 3: output projection (f32x2)  d_out = g_O(8192x256) @ Wo + bo
// =====================================================================
__global__ __launch_bounds__(256) void out_kernel(const float* __restrict__ Wo,
                                                  const float* __restrict__ bo,
                                                  float* __restrict__ out)
{
    __shared__ float As[64 * 20];
    __shared__ float Bst[64 * 18];
    const int m0 = blockIdx.x * 64;
    const int n0 = blockIdx.y * 64;
    const int tid = threadIdx.x;
    const int tx = tid & 15, ty = tid >> 4;

    ull acc2[4][4] = {};
    for (int k0 = 0; k0 < DM; k0 += 16) {
        {
            int i = tid >> 2, c = tid & 3;
            float4 a = *(const float4*)&g_O[(size_t)(m0 + i) * DM + k0 + c * 4];
            *(float4*)&As[i * 20 + c * 4] = a;
            int kk = tid >> 4, c2 = tid & 15;
            float4 w = *(const float4*)&Wo[(size_t)(k0 + kk) * DM + n0 + c2 * 4];
            Bst[(c2 * 4 + 0) * 18 + kk] = w.x;
            Bst[(c2 * 4 + 1) * 18 + kk] = w.y;
            Bst[(c2 * 4 + 2) * 18 + kk] = w.z;
            Bst[(c2 * 4 + 3) * 18 + kk] = w.w;
        }
        __syncthreads();
        #pragma unroll
        for (int p = 0; p < 8; p++) {
            ull a2[4], b2[4];
            #pragma unroll
            for (int ii = 0; ii < 4; ii++) a2[ii] = *(const ull*)&As[(ty * 4 + ii) * 20 + 2 * p];
            #pragma unroll
            for (int jj = 0; jj < 4; jj++) b2[jj] = *(const ull*)&Bst[(tx + 16 * jj) * 18 + 2 * p];
            #pragma unroll
            for (int ii = 0; ii < 4; ii++)
                #pragma unroll
                for (int jj = 0; jj < 4; jj++)
                    FMA2(acc2[ii][jj], a2[ii], b2[jj]);
        }
        __syncthreads();
    }

    #pragma unroll
    for (int ii = 0; ii < 4; ii++) {
        int m = m0 + ty * 4 + ii;
        #pragma unroll
        for (int jj = 0; jj < 4; jj++) {
            int col = tx + 16 * jj;
            float2 v = unpack2(acc2[ii][jj]);
            out[(size_t)m * DM + n0 + col] = v.x + v.y + bo[n0 + col];
        }
    }
}

// =====================================================================
extern "C" void kernel_launch(void* const* d_in, const int* in_sizes, int n_in,
                              void* d_out, int out_size)
{
    const float* query = (const float*)d_in[0];
    const float* key_  = (const float*)d_in[1];
    const float* value = (const float*)d_in[2];
    const float* Wq    = (const float*)d_in[3];
    const float* bq    = (const float*)d_in[4];
    const float* Wk    = (const float*)d_in[5];
    const float* bk    = (const float*)d_in[6];
    const float* Wv    = (const float*)d_in[7];
    const float* bv    = (const float*)d_in[8];
    const float* W2    = (const float*)d_in[9];
    const float* alpha = (const float*)d_in[10];
    const float* Wo    = (const float*)d_in[11];
    const float* bo    = (const float*)d_in[12];
    float* out = (float*)d_out;

    cudaFuncSetAttribute(prep_kernel, cudaFuncAttributeMaxDynamicSharedMemorySize, PREP_SMEM);
    cudaFuncSetAttribute(attn_kernel, cudaFuncAttributeMaxDynamicSharedMemorySize, ATTN_SMEM);

    prep_kernel<<<NH, 256, PREP_SMEM>>>(W2, alpha, Wk, bk);
    proj_kernel<<<dim3(128, 4, 3), 256>>>(query, key_, value, Wq, bq, Wv, bv);
    attn_kernel<<<dim3(32, BHT), 256, ATTN_SMEM>>>();
    out_kernel<<<dim3(128, 4), 256>>>(Wo, bo, out);
}

// round 6
// speedup vs baseline: 2.3465x; 2.3465x over previous
#include <cuda_runtime.h>
#include <math.h>

#define B_   4
#define SEQ  2048
#define DM   256
#define NH   4
#define DH   64
#define BHT  16       // B_*NH

// ---------------- scratch (device globals; no allocation) ----------------
__device__ float g_Q [BHT * SEQ * DH];   // [bh][s][64]  (pre-scaled by 1/8)
__device__ float g_K [BHT * SEQ * DH];   // effective K = K·G^T
__device__ float g_V [BHT * SEQ * DH];
__device__ float g_O [B_  * SEQ * DM];   // attn output
__device__ float g_Wk[DM * DM];          // folded Wk_eff
__device__ float g_bk[DM];               // folded bk_eff

// ---------------- tf32 helpers ----------------
__device__ __forceinline__ unsigned f2tf(float f) {
    unsigned u; asm("cvt.rna.tf32.f32 %0, %1;" : "=r"(u) : "f"(f)); return u;
}
__device__ __forceinline__ void mma8(float c[4], const unsigned a[4], const unsigned b[2]) {
    asm volatile(
        "mma.sync.aligned.m16n8k8.row.col.f32.tf32.tf32.f32 "
        "{%0,%1,%2,%3}, {%4,%5,%6,%7}, {%8,%9}, {%0,%1,%2,%3};\n"
        : "+f"(c[0]), "+f"(c[1]), "+f"(c[2]), "+f"(c[3])
        : "r"(a[0]), "r"(a[1]), "r"(a[2]), "r"(a[3]), "r"(b[0]), "r"(b[1]));
}

// =====================================================================
// Kernel 0: prep — fold TT interaction into Wk.
//   M_h[d,e] = sum_{a,r} W2[h,d,a,r] * W2[h,a,e,r];  G = I + (alpha/64) M
// =====================================================================
#define PREP_SMEM ((64 * 256 + 64 * 65) * 4)

__global__ __launch_bounds__(256) void prep_kernel(const float* __restrict__ W2,
                                                   const float* __restrict__ alpha_p,
                                                   const float* __restrict__ Wk,
                                                   const float* __restrict__ bk)
{
    extern __shared__ float sm[];
    float* Ws = sm;              // 64 x 256
    float* Gs = sm + 64 * 256;   // 64 x 65
    const int h = blockIdx.x;
    const int tid = threadIdx.x;
    const float* W2h = W2 + (size_t)h * 64 * 256;

    for (int idx = tid; idx < 64 * 256; idx += 256) Ws[idx] = W2h[idx];
    __syncthreads();

    const float c = alpha_p[0] * (1.0f / 64.0f);
    for (int idx = tid; idx < 64 * 64; idx += 256) {
        int d = idx >> 6, e = idx & 63;
        float s = 0.f;
        #pragma unroll 8
        for (int a = 0; a < 64; a++) {
            float4 wa = *(const float4*)&Ws[d * 256 + a * 4];
            float4 wb = *(const float4*)&Ws[a * 256 + e * 4];
            s += wa.x * wb.x + wa.y * wb.y + wa.z * wb.z + wa.w * wb.w;
        }
        Gs[d * 65 + e] = c * s + ((d == e) ? 1.0f : 0.0f);
    }
    __syncthreads();

    {
        const int cr = tid;
        float kin[64];
        #pragma unroll
        for (int e = 0; e < 64; e++) kin[e] = Wk[(size_t)cr * DM + h * 64 + e];
        for (int d = 0; d < 64; d++) {
            float s = 0.f;
            #pragma unroll
            for (int e = 0; e < 64; e++) s += kin[e] * Gs[d * 65 + e];
            g_Wk[(size_t)cr * DM + h * 64 + d] = s;
        }
    }
    if (tid < 64) {
        int d = tid;
        float s = 0.f;
        #pragma unroll
        for (int e = 0; e < 64; e++) s += bk[h * 64 + e] * Gs[d * 65 + e];
        g_bk[h * 64 + d] = s;
    }
}

// =====================================================================
// Kernel 1: QKV projection GEMM (fp32, R3-proven).  z=0:Q(x1/8) 1:K(folded) 2:V
// =====================================================================
__global__ __launch_bounds__(256) void proj_kernel(
    const float* __restrict__ Xq, const float* __restrict__ Xk, const float* __restrict__ Xv,
    const float* __restrict__ Wq, const float* __restrict__ bq,
    const float* __restrict__ Wv, const float* __restrict__ bv)
{
    __shared__ float As[64 * 17];
    __shared__ float Bs[16 * 68];
    const int z = blockIdx.z;
    const float* X    = (z == 0) ? Xq : (z == 1) ? Xk : Xv;
    const float* W    = (z == 0) ? Wq : (z == 1) ? g_Wk : Wv;
    const float* bias = (z == 0) ? bq : (z == 1) ? g_bk : bv;
    const int m0 = blockIdx.x * 64;
    const int n0 = blockIdx.y * 64;
    const int tid = threadIdx.x;
    const int tx = tid & 15, ty = tid >> 4;

    float acc[4][4] = {};
    for (int k0 = 0; k0 < DM; k0 += 16) {
        {
            int i = tid >> 2, c = tid & 3;
            float4 a = *(const float4*)&X[(size_t)(m0 + i) * DM + k0 + c * 4];
            As[i * 17 + c * 4 + 0] = a.x;
            As[i * 17 + c * 4 + 1] = a.y;
            As[i * 17 + c * 4 + 2] = a.z;
            As[i * 17 + c * 4 + 3] = a.w;
            int kk = tid >> 4, c2 = tid & 15;
            *(float4*)&Bs[kk * 68 + c2 * 4] =
                *(const float4*)&W[(size_t)(k0 + kk) * DM + n0 + c2 * 4];
        }
        __syncthreads();
        #pragma unroll
        for (int kk = 0; kk < 16; kk++) {
            float a0 = As[(ty * 4 + 0) * 17 + kk];
            float a1 = As[(ty * 4 + 1) * 17 + kk];
            float a2 = As[(ty * 4 + 2) * 17 + kk];
            float a3 = As[(ty * 4 + 3) * 17 + kk];
            float4 b = *(float4*)&Bs[kk * 68 + tx * 4];
            acc[0][0] += a0 * b.x; acc[0][1] += a0 * b.y; acc[0][2] += a0 * b.z; acc[0][3] += a0 * b.w;
            acc[1][0] += a1 * b.x; acc[1][1] += a1 * b.y; acc[1][2] += a1 * b.z; acc[1][3] += a1 * b.w;
            acc[2][0] += a2 * b.x; acc[2][1] += a2 * b.y; acc[2][2] += a2 * b.z; acc[2][3] += a2 * b.w;
            acc[3][0] += a3 * b.x; acc[3][1] += a3 * b.y; acc[3][2] += a3 * b.z; acc[3][3] += a3 * b.w;
        }
        __syncthreads();
    }

    const int h = n0 >> 6;
    float* dst = (z == 0) ? g_Q : (z == 1) ? g_K : g_V;
    const float sc = (z == 0) ? 0.125f : 1.0f;
    #pragma unroll
    for (int ii = 0; ii < 4; ii++) {
        int m = m0 + ty * 4 + ii;
        int b = m >> 11, s = m & (SEQ - 1);
        float4 r;
        r.x = (acc[ii][0] + bias[n0 + tx * 4 + 0]) * sc;
        r.y = (acc[ii][1] + bias[n0 + tx * 4 + 1]) * sc;
        r.z = (acc[ii][2] + bias[n0 + tx * 4 + 2]) * sc;
        r.w = (acc[ii][3] + bias[n0 + tx * 4 + 3]) * sc;
        *(float4*)&dst[(size_t)((b * NH + h) * SEQ + s) * DH + tx * 4] = r;
    }
}

// =====================================================================
// Kernel 2: flash attention via mma.sync m16n8k8 tf32.
// Block: 128 q-rows, 8 warps x 16 rows.  K/V tiles of 64 keys.
// Qs (tf32) overlaid by Ps after Q fragments move to registers.
// Strides: Q/K/P 68 (bank = 4*gid+tig), V 72 (bank = 8*tig+gid) — conflict-free.
// =====================================================================
#define ATTN_SMEM ((128 * 68 + 64 * 68 + 64 * 72) * 4)   // 70,656 B

__global__ __launch_bounds__(256, 2) void attn_kernel()
{
    extern __shared__ float sm[];
    float* Qs = sm;                   // 128x68 tf32 bits; becomes Ps after prologue
    float* Ps = sm;                   // 128x68 (tf32 bits of P)
    float* Ks = sm + 128 * 68;        // 64x68 tf32 bits
    float* Vs = Ks + 64 * 68;         // 64x72 tf32 bits
    const int bh = blockIdx.y;
    const int qt = blockIdx.x;
    const int tid  = threadIdx.x;
    const int w    = tid >> 5;
    const int lane = tid & 31;
    const int gid  = lane >> 2;       // 0..7
    const int tig  = lane & 3;        // 0..3

    // ---- prologue: load Q tile (128x64) as tf32 into smem ----
    const float* Qg = g_Q + (size_t)(bh * SEQ + qt * 128) * DH;
    #pragma unroll
    for (int it = 0; it < 8; it++) {
        int idx = tid + it * 256;
        int i = idx >> 4, c = idx & 15;
        float4 q = *(const float4*)&Qg[i * DH + c * 4];
        float* d = &Qs[i * 68 + c * 4];
        d[0] = __uint_as_float(f2tf(q.x));
        d[1] = __uint_as_float(f2tf(q.y));
        d[2] = __uint_as_float(f2tf(q.z));
        d[3] = __uint_as_float(f2tf(q.w));
    }
    __syncthreads();

    // ---- move Q fragments to registers (held for whole kernel) ----
    const int qrow = w * 16 + gid;
    unsigned aq[8][4];
    #pragma unroll
    for (int k0 = 0; k0 < 8; k0++) {
        aq[k0][0] = __float_as_uint(Qs[qrow * 68 + k0 * 8 + tig]);
        aq[k0][1] = __float_as_uint(Qs[(qrow + 8) * 68 + k0 * 8 + tig]);
        aq[k0][2] = __float_as_uint(Qs[qrow * 68 + k0 * 8 + tig + 4]);
        aq[k0][3] = __float_as_uint(Qs[(qrow + 8) * 68 + k0 * 8 + tig + 4]);
    }

    float m0 = -1e30f, m1 = -1e30f, l0 = 0.f, l1 = 0.f;
    float o[8][4] = {};

    for (int kt = 0; kt < 32; kt++) {
        // ---- load K/V tile (64x64 each), cvt to tf32 ----
        const float* Kg = g_K + (size_t)(bh * SEQ + kt * 64) * DH;
        const float* Vg = g_V + (size_t)(bh * SEQ + kt * 64) * DH;
        #pragma unroll
        for (int it = 0; it < 4; it++) {
            int idx = tid + it * 256;
            int i = idx >> 4, c = idx & 15;
            float4 kk = *(const float4*)&Kg[i * DH + c * 4];
            float* dk = &Ks[i * 68 + c * 4];
            dk[0] = __uint_as_float(f2tf(kk.x));
            dk[1] = __uint_as_float(f2tf(kk.y));
            dk[2] = __uint_as_float(f2tf(kk.z));
            dk[3] = __uint_as_float(f2tf(kk.w));
            float4 vv = *(const float4*)&Vg[i * DH + c * 4];
            float* dv = &Vs[i * 72 + c * 4];
            dv[0] = __uint_as_float(f2tf(vv.x));
            dv[1] = __uint_as_float(f2tf(vv.y));
            dv[2] = __uint_as_float(f2tf(vv.z));
            dv[3] = __uint_as_float(f2tf(vv.w));
        }
        __syncthreads();

        // ---- S[16x64] = Q . K^T ----
        float s[8][4] = {};
        #pragma unroll
        for (int k0 = 0; k0 < 8; k0++) {
            #pragma unroll
            for (int n0 = 0; n0 < 8; n0++) {
                unsigned b[2];
                const float* kp = &Ks[(n0 * 8 + gid) * 68 + k0 * 8 + tig];
                b[0] = __float_as_uint(kp[0]);
                b[1] = __float_as_uint(kp[4]);
                mma8(s[n0], aq[k0], b);
            }
        }

        // ---- online softmax (rows qrow and qrow+8) ----
        float rx0 = -1e30f, rx1 = -1e30f;
        #pragma unroll
        for (int n0 = 0; n0 < 8; n0++) {
            rx0 = fmaxf(rx0, fmaxf(s[n0][0], s[n0][1]));
            rx1 = fmaxf(rx1, fmaxf(s[n0][2], s[n0][3]));
        }
        rx0 = fmaxf(rx0, __shfl_xor_sync(0xffffffffu, rx0, 1));
        rx0 = fmaxf(rx0, __shfl_xor_sync(0xffffffffu, rx0, 2));
        rx1 = fmaxf(rx1, __shfl_xor_sync(0xffffffffu, rx1, 1));
        rx1 = fmaxf(rx1, __shfl_xor_sync(0xffffffffu, rx1, 2));
        float mn0 = fmaxf(m0, rx0), mn1 = fmaxf(m1, rx1);
        float corr0 = __expf(m0 - mn0), corr1 = __expf(m1 - mn1);
        m0 = mn0; m1 = mn1;
        float rs0 = 0.f, rs1 = 0.f;
        #pragma unroll
        for (int n0 = 0; n0 < 8; n0++) {
            float p0 = __expf(s[n0][0] - mn0);
            float p1 = __expf(s[n0][1] - mn0);
            float p2 = __expf(s[n0][2] - mn1);
            float p3 = __expf(s[n0][3] - mn1);
            rs0 += p0 + p1; rs1 += p2 + p3;
            o[n0][0] *= corr0; o[n0][1] *= corr0;
            o[n0][2] *= corr1; o[n0][3] *= corr1;
            *(float2*)&Ps[qrow * 68 + n0 * 8 + 2 * tig] =
                make_float2(__uint_as_float(f2tf(p0)), __uint_as_float(f2tf(p1)));
            *(float2*)&Ps[(qrow + 8) * 68 + n0 * 8 + 2 * tig] =
                make_float2(__uint_as_float(f2tf(p2)), __uint_as_float(f2tf(p3)));
        }
        rs0 += __shfl_xor_sync(0xffffffffu, rs0, 1);
        rs0 += __shfl_xor_sync(0xffffffffu, rs0, 2);
        rs1 += __shfl_xor_sync(0xffffffffu, rs1, 1);
        rs1 += __shfl_xor_sync(0xffffffffu, rs1, 2);
        l0 = l0 * corr0 + rs0;
        l1 = l1 * corr1 + rs1;
        __syncwarp();

        // ---- O[16x64] += P . V ----
        #pragma unroll
        for (int k0 = 0; k0 < 8; k0++) {
            unsigned ap[4];
            ap[0] = __float_as_uint(Ps[qrow * 68 + k0 * 8 + tig]);
            ap[1] = __float_as_uint(Ps[(qrow + 8) * 68 + k0 * 8 + tig]);
            ap[2] = __float_as_uint(Ps[qrow * 68 + k0 * 8 + tig + 4]);
            ap[3] = __float_as_uint(Ps[(qrow + 8) * 68 + k0 * 8 + tig + 4]);
            #pragma unroll
            for (int n0 = 0; n0 < 8; n0++) {
                unsigned b[2];
                b[0] = __float_as_uint(Vs[(k0 * 8 + tig) * 72 + n0 * 8 + gid]);
                b[1] = __float_as_uint(Vs[(k0 * 8 + tig + 4) * 72 + n0 * 8 + gid]);
                mma8(o[n0], ap, b);
            }
        }
        __syncthreads();
    }

    // ---- epilogue: normalize, write g_O ----
    const float inv0 = 1.0f / l0, inv1 = 1.0f / l1;
    const int bb = bh >> 2, h = bh & 3;
    const int r0 = qt * 128 + qrow;
    size_t base0 = (size_t)(bb * SEQ + r0) * DM + h * 64;
    size_t base1 = base0 + (size_t)8 * DM;
    #pragma unroll
    for (int n0 = 0; n0 < 8; n0++) {
        *(float2*)&g_O[base0 + n0 * 8 + 2 * tig] =
            make_float2(o[n0][0] * inv0, o[n0][1] * inv0);
        *(float2*)&g_O[base1 + n0 * 8 + 2 * tig] =
            make_float2(o[n0][2] * inv1, o[n0][3] * inv1);
    }
}

// =====================================================================
// Kernel 3: output projection (fp32, R3-proven)  d_out = g_O @ Wo + bo
// =====================================================================
__global__ __launch_bounds__(256) void out_kernel(const float* __restrict__ Wo,
                                                  const float* __restrict__ bo,
                                                  float* __restrict__ out)
{
    __shared__ float As[64 * 17];
    __shared__ float Bs[16 * 68];
    const int m0 = blockIdx.x * 64;
    const int n0 = blockIdx.y * 64;
    const int tid = threadIdx.x;
    const int tx = tid & 15, ty = tid >> 4;

    float acc[4][4] = {};
    for (int k0 = 0; k0 < DM; k0 += 16) {
        {
            int i = tid >> 2, c = tid & 3;
            float4 a = *(const float4*)&g_O[(size_t)(m0 + i) * DM + k0 + c * 4];
            As[i * 17 + c * 4 + 0] = a.x;
            As[i * 17 + c * 4 + 1] = a.y;
            As[i * 17 + c * 4 + 2] = a.z;
            As[i * 17 + c * 4 + 3] = a.w;
            int kk = tid >> 4, c2 = tid & 15;
            *(float4*)&Bs[kk * 68 + c2 * 4] =
                *(const float4*)&Wo[(size_t)(k0 + kk) * DM + n0 + c2 * 4];
        }
        __syncthreads();
        #pragma unroll
        for (int kk = 0; kk < 16; kk++) {
            float a0 = As[(ty * 4 + 0) * 17 + kk];
            float a1 = As[(ty * 4 + 1) * 17 + kk];
            float a2 = As[(ty * 4 + 2) * 17 + kk];
            float a3 = As[(ty * 4 + 3) * 17 + kk];
            float4 b = *(float4*)&Bs[kk * 68 + tx * 4];
            acc[0][0] += a0 * b.x; acc[0][1] += a0 * b.y; acc[0][2] += a0 * b.z; acc[0][3] += a0 * b.w;
            acc[1][0] += a1 * b.x; acc[1][1] += a1 * b.y; acc[1][2] += a1 * b.z; acc[1][3] += a1 * b.w;
            acc[2][0] += a2 * b.x; acc[2][1] += a2 * b.y; acc[2][2] += a2 * b.z; acc[2][3] += a2 * b.w;
            acc[3][0] += a3 * b.x; acc[3][1] += a3 * b.y; acc[3][2] += a3 * b.z; acc[3][3] += a3 * b.w;
        }
        __syncthreads();
    }

    #pragma unroll
    for (int ii = 0; ii < 4; ii++) {
        int m = m0 + ty * 4 + ii;
        float4 r;
        r.x = acc[ii][0] + bo[n0 + tx * 4 + 0];
        r.y = acc[ii][1] + bo[n0 + tx * 4 + 1];
        r.z = acc[ii][2] + bo[n0 + tx * 4 + 2];
        r.w = acc[ii][3] + bo[n0 + tx * 4 + 3];
        *(float4*)&out[(size_t)m * DM + n0 + tx * 4] = r;
    }
}

// =====================================================================
extern "C" void kernel_launch(void* const* d_in, const int* in_sizes, int n_in,
                              void* d_out, int out_size)
{
    const float* query = (const float*)d_in[0];
    const float* key_  = (const float*)d_in[1];
    const float* value = (const float*)d_in[2];
    const float* Wq    = (const float*)d_in[3];
    const float* bq    = (const float*)d_in[4];
    const float* Wk    = (const float*)d_in[5];
    const float* bk    = (const float*)d_in[6];
    const float* Wv    = (const float*)d_in[7];
    const float* bv    = (const float*)d_in[8];
    const float* W2    = (const float*)d_in[9];
    const float* alpha = (const float*)d_in[10];
    const float* Wo    = (const float*)d_in[11];
    const float* bo    = (const float*)d_in[12];
    float* out = (float*)d_out;

    cudaFuncSetAttribute(prep_kernel, cudaFuncAttributeMaxDynamicSharedMemorySize, PREP_SMEM);
    cudaFuncSetAttribute(attn_kernel, cudaFuncAttributeMaxDynamicSharedMemorySize, ATTN_SMEM);

    prep_kernel<<<NH, 256, PREP_SMEM>>>(W2, alpha, Wk, bk);
    proj_kernel<<<dim3(128, 4, 3), 256>>>(query, key_, value, Wq, bq, Wv, bv);
    attn_kernel<<<dim3(16, BHT), 256, ATTN_SMEM>>>();
    out_kernel<<<dim3(128, 4), 256>>>(Wo, bo, out);
}

// round 7
// speedup vs baseline: 2.5295x; 1.0780x over previous
#include <cuda_runtime.h>
#include <cuda_bf16.h>
#include <math.h>

#define B_   4
#define SEQ  2048
#define DM   256
#define NH   4
#define DH   64
#define BHT  16       // B_*NH

// ---------------- scratch (device globals; no allocation) ----------------
__device__ float g_Q [BHT * SEQ * DH];   // [bh][s][64] tf32-rounded, k-permuted, x1/8
__device__ float g_K [BHT * SEQ * DH];   // effective K = K·G^T, tf32-rounded, k-permuted
__device__ float g_V [BHT * SEQ * DH];   // tf32-rounded, plain layout
__device__ float g_O [B_  * SEQ * DM];   // attn output
__device__ float g_Wk[DM * DM];          // folded Wk_eff
__device__ float g_bk[DM];               // folded bk_eff

// ---------------- helpers ----------------
__device__ __forceinline__ unsigned f2tf(float f) {
    unsigned u; asm("cvt.rna.tf32.f32 %0, %1;" : "=r"(u) : "f"(f)); return u;
}
__device__ __forceinline__ void mma8(float c[4], const unsigned a[4], unsigned b0, unsigned b1) {
    asm volatile(
        "mma.sync.aligned.m16n8k8.row.col.f32.tf32.tf32.f32 "
        "{%0,%1,%2,%3}, {%4,%5,%6,%7}, {%8,%9}, {%0,%1,%2,%3};\n"
        : "+f"(c[0]), "+f"(c[1]), "+f"(c[2]), "+f"(c[3])
        : "r"(a[0]), "r"(a[1]), "r"(a[2]), "r"(a[3]), "r"(b0), "r"(b1));
}
__device__ __forceinline__ void mmabf(float c[4], const unsigned a[4], unsigned b0, unsigned b1) {
    asm volatile(
        "mma.sync.aligned.m16n8k16.row.col.f32.bf16.bf16.f32 "
        "{%0,%1,%2,%3}, {%4,%5,%6,%7}, {%8,%9}, {%0,%1,%2,%3};\n"
        : "+f"(c[0]), "+f"(c[1]), "+f"(c[2]), "+f"(c[3])
        : "r"(a[0]), "r"(a[1]), "r"(a[2]), "r"(a[3]), "r"(b0), "r"(b1));
}
__device__ __forceinline__ void bsplit(float x, unsigned short& hi, unsigned short& lo) {
    __nv_bfloat16 h = __float2bfloat16_rn(x);
    float r = x - __bfloat162float(h);
    __nv_bfloat16 l = __float2bfloat16_rn(r);
    hi = *(unsigned short*)&h;
    lo = *(unsigned short*)&l;
}
// permute within 8-group so (k, k+4) land adjacent: j<4 -> 2j ; j>=4 -> 2j-7
__device__ __forceinline__ int p8(int j) { return (j < 4) ? 2 * j : 2 * j - 7; }

// =====================================================================
// Kernel 0: prep — fold TT interaction into Wk.
//   M_h[d,e] = sum_{a,r} W2[h,d,a,r] * W2[h,a,e,r];  G = I + (alpha/64) M
// =====================================================================
#define PREP_SMEM ((64 * 256 + 64 * 65) * 4)

__global__ __launch_bounds__(256) void prep_kernel(const float* __restrict__ W2,
                                                   const float* __restrict__ alpha_p,
                                                   const float* __restrict__ Wk,
                                                   const float* __restrict__ bk)
{
    extern __shared__ float sm[];
    float* Ws = sm;              // 64 x 256
    float* Gs = sm + 64 * 256;   // 64 x 65
    const int h = blockIdx.x;
    const int tid = threadIdx.x;
    const float* W2h = W2 + (size_t)h * 64 * 256;

    for (int idx = tid; idx < 64 * 256; idx += 256) Ws[idx] = W2h[idx];
    __syncthreads();

    const float c = alpha_p[0] * (1.0f / 64.0f);
    for (int idx = tid; idx < 64 * 64; idx += 256) {
        int d = idx >> 6, e = idx & 63;
        float s = 0.f;
        #pragma unroll 8
        for (int a = 0; a < 64; a++) {
            float4 wa = *(const float4*)&Ws[d * 256 + a * 4];
            float4 wb = *(const float4*)&Ws[a * 256 + e * 4];
            s += wa.x * wb.x + wa.y * wb.y + wa.z * wb.z + wa.w * wb.w;
        }
        Gs[d * 65 + e] = c * s + ((d == e) ? 1.0f : 0.0f);
    }
    __syncthreads();

    {
        const int cr = tid;
        float kin[64];
        #pragma unroll
        for (int e = 0; e < 64; e++) kin[e] = Wk[(size_t)cr * DM + h * 64 + e];
        for (int d = 0; d < 64; d++) {
            float s = 0.f;
            #pragma unroll
            for (int e = 0; e < 64; e++) s += kin[e] * Gs[d * 65 + e];
            g_Wk[(size_t)cr * DM + h * 64 + d] = s;
        }
    }
    if (tid < 64) {
        int d = tid;
        float s = 0.f;
        #pragma unroll
        for (int e = 0; e < 64; e++) s += bk[h * 64 + e] * Gs[d * 65 + e];
        g_bk[h * 64 + d] = s;
    }
}

// =====================================================================
// Kernel 1: QKV projection — bf16-split mma (Ah·Bh + Al·Bh + Ah·Bl).
// 64x64 tile, 8 warps: warp w -> m-strip (w&3)*16, n-half (w>>2)*32 (4 n-tiles).
// Epilogue: Q/K -> tf32-rounded, k-permuted scatter; V -> tf32-rounded plain.
// =====================================================================
__global__ __launch_bounds__(256) void proj_kernel(
    const float* __restrict__ Xq, const float* __restrict__ Xk, const float* __restrict__ Xv,
    const float* __restrict__ Wq, const float* __restrict__ bq,
    const float* __restrict__ Wv, const float* __restrict__ bv)
{
    __shared__ unsigned short Ah[64 * 18], Al[64 * 18];
    __shared__ unsigned short Bh[64 * 18], Bl[64 * 18];
    const int z = blockIdx.z;
    const float* X    = (z == 0) ? Xq : (z == 1) ? Xk : Xv;
    const float* W    = (z == 0) ? Wq : (z == 1) ? g_Wk : Wv;
    const float* bias = (z == 0) ? bq : (z == 1) ? g_bk : bv;
    const int m0 = blockIdx.x * 64;
    const int n0 = blockIdx.y * 64;
    const int tid  = threadIdx.x;
    const int w    = tid >> 5;
    const int lane = tid & 31;
    const int gid  = lane >> 2, tig = lane & 3;
    const int mrow = (w & 3) * 16;
    const int nc0  = (w >> 2) * 32;

    float acc[4][4] = {};
    for (int k0 = 0; k0 < DM; k0 += 16) {
        {
            int i = tid >> 2, c = tid & 3;
            float4 a = *(const float4*)&X[(size_t)(m0 + i) * DM + k0 + c * 4];
            float av[4] = {a.x, a.y, a.z, a.w};
            #pragma unroll
            for (int u = 0; u < 4; u++)
                bsplit(av[u], Ah[i * 18 + c * 4 + u], Al[i * 18 + c * 4 + u]);
            int kk = tid >> 4, c2 = tid & 15;
            float4 wv = *(const float4*)&W[(size_t)(k0 + kk) * DM + n0 + c2 * 4];
            float wf[4] = {wv.x, wv.y, wv.z, wv.w};
            #pragma unroll
            for (int u = 0; u < 4; u++)
                bsplit(wf[u], Bh[(c2 * 4 + u) * 18 + kk], Bl[(c2 * 4 + u) * 18 + kk]);
        }
        __syncthreads();
        unsigned ah[4], al[4];
        ah[0] = *(const unsigned*)&Ah[(mrow + gid)     * 18 + 2 * tig];
        ah[1] = *(const unsigned*)&Ah[(mrow + gid + 8) * 18 + 2 * tig];
        ah[2] = *(const unsigned*)&Ah[(mrow + gid)     * 18 + 8 + 2 * tig];
        ah[3] = *(const unsigned*)&Ah[(mrow + gid + 8) * 18 + 8 + 2 * tig];
        al[0] = *(const unsigned*)&Al[(mrow + gid)     * 18 + 2 * tig];
        al[1] = *(const unsigned*)&Al[(mrow + gid + 8) * 18 + 2 * tig];
        al[2] = *(const unsigned*)&Al[(mrow + gid)     * 18 + 8 + 2 * tig];
        al[3] = *(const unsigned*)&Al[(mrow + gid + 8) * 18 + 8 + 2 * tig];
        #pragma unroll
        for (int nt = 0; nt < 4; nt++) {
            int n = nc0 + nt * 8 + gid;
            unsigned bh0 = *(const unsigned*)&Bh[n * 18 + 2 * tig];
            unsigned bh1 = *(const unsigned*)&Bh[n * 18 + 8 + 2 * tig];
            unsigned bl0 = *(const unsigned*)&Bl[n * 18 + 2 * tig];
            unsigned bl1 = *(const unsigned*)&Bl[n * 18 + 8 + 2 * tig];
            mmabf(acc[nt], ah, bh0, bh1);
            mmabf(acc[nt], al, bh0, bh1);
            mmabf(acc[nt], ah, bl0, bl1);
        }
        __syncthreads();
    }

    const int h = n0 >> 6;
    float* dst = (z == 0) ? g_Q : (z == 1) ? g_K : g_V;
    const float sc = (z == 0) ? 0.125f : 1.0f;
    const int r0 = m0 + mrow + gid;
    #pragma unroll
    for (int nt = 0; nt < 4; nt++) {
        int ch0 = nc0 + nt * 8 + 2 * tig;     // head-local col
        int ch1 = ch0 + 1;
        float v[2][2];
        v[0][0] = (acc[nt][0] + bias[n0 + ch0]) * sc;
        v[0][1] = (acc[nt][1] + bias[n0 + ch1]) * sc;
        v[1][0] = (acc[nt][2] + bias[n0 + ch0]) * sc;
        v[1][1] = (acc[nt][3] + bias[n0 + ch1]) * sc;
        #pragma unroll
        for (int rr = 0; rr < 2; rr++) {
            int m = r0 + rr * 8;
            int b = m >> 11, s = m & (SEQ - 1);
            size_t base = (size_t)((b * NH + h) * SEQ + s) * DH;
            float t0 = __uint_as_float(f2tf(v[rr][0]));
            float t1 = __uint_as_float(f2tf(v[rr][1]));
            if (z < 2) {   // permuted k layout for Q/K
                dst[base + (ch0 & ~7) + p8(ch0 & 7)] = t0;
                dst[base + (ch1 & ~7) + p8(ch1 & 7)] = t1;
            } else {
                dst[base + ch0] = t0;
                dst[base + ch1] = t1;
            }
        }
    }
}

// =====================================================================
// Kernel 2: flash attention via mma.sync m16n8k8 tf32.
// g_Q/g_K pre-rounded + k-permuted -> S-phase fragments are LDS.64.
// Qs/Ks stride 72 (8B pair-bank = 4*gid+tig, conflict-free); Vs 72; Ps 68.
// =====================================================================
#define ATTN_SMEM ((128 * 72 + 64 * 72 + 64 * 72) * 4)   // 73,728 B

__global__ __launch_bounds__(256, 2) void attn_kernel()
{
    extern __shared__ float sm[];
    float* Qs = sm;                   // 128x72; becomes Ps after prologue
    float* Ps = sm;                   // 128x68 view (tf32 bits of P)
    float* Ks = sm + 128 * 72;        // 64x72
    float* Vs = Ks + 64 * 72;         // 64x72
    const int bh = blockIdx.y;
    const int qt = blockIdx.x;
    const int tid  = threadIdx.x;
    const int w    = tid >> 5;
    const int lane = tid & 31;
    const int gid  = lane >> 2;       // 0..7
    const int tig  = lane & 3;        // 0..3

    // ---- prologue: copy Q tile (pre-rounded, permuted) ----
    const float* Qg = g_Q + (size_t)(bh * SEQ + qt * 128) * DH;
    #pragma unroll
    for (int it = 0; it < 8; it++) {
        int idx = tid + it * 256;
        int i = idx >> 4, c = idx & 15;
        *(float4*)&Qs[i * 72 + c * 4] = *(const float4*)&Qg[i * DH + c * 4];
    }
    __syncthreads();

    // ---- Q fragments to registers (LDS.64 pairs) ----
    const int qrow = w * 16 + gid;
    unsigned aq[8][4];
    #pragma unroll
    for (int k0 = 0; k0 < 8; k0++) {
        uint2 qa = *(const uint2*)&Qs[qrow * 72 + k0 * 8 + 2 * tig];
        uint2 qb = *(const uint2*)&Qs[(qrow + 8) * 72 + k0 * 8 + 2 * tig];
        aq[k0][0] = qa.x; aq[k0][1] = qb.x; aq[k0][2] = qa.y; aq[k0][3] = qb.y;
    }

    float m0 = -1e30f, m1 = -1e30f, l0 = 0.f, l1 = 0.f;
    float o[8][4] = {};

    for (int kt = 0; kt < 32; kt++) {
        const float* Kg = g_K + (size_t)(bh * SEQ + kt * 64) * DH;
        const float* Vg = g_V + (size_t)(bh * SEQ + kt * 64) * DH;
        #pragma unroll
        for (int it = 0; it < 4; it++) {
            int idx = tid + it * 256;
            int i = idx >> 4, c = idx & 15;
            *(float4*)&Ks[i * 72 + c * 4] = *(const float4*)&Kg[i * DH + c * 4];
            *(float4*)&Vs[i * 72 + c * 4] = *(const float4*)&Vg[i * DH + c * 4];
        }
        __syncthreads();

        // ---- S[16x64] = Q . K^T  (b fragment = one LDS.64) ----
        float s[8][4] = {};
        #pragma unroll
        for (int k0 = 0; k0 < 8; k0++) {
            #pragma unroll
            for (int n0 = 0; n0 < 8; n0++) {
                uint2 bb = *(const uint2*)&Ks[(n0 * 8 + gid) * 72 + k0 * 8 + 2 * tig];
                mma8(s[n0], aq[k0], bb.x, bb.y);
            }
        }

        // ---- online softmax (rows qrow and qrow+8) ----
        float rx0 = -1e30f, rx1 = -1e30f;
        #pragma unroll
        for (int n0 = 0; n0 < 8; n0++) {
            rx0 = fmaxf(rx0, fmaxf(s[n0][0], s[n0][1]));
            rx1 = fmaxf(rx1, fmaxf(s[n0][2], s[n0][3]));
        }
        rx0 = fmaxf(rx0, __shfl_xor_sync(0xffffffffu, rx0, 1));
        rx0 = fmaxf(rx0, __shfl_xor_sync(0xffffffffu, rx0, 2));
        rx1 = fmaxf(rx1, __shfl_xor_sync(0xffffffffu, rx1, 1));
        rx1 = fmaxf(rx1, __shfl_xor_sync(0xffffffffu, rx1, 2));
        float mn0 = fmaxf(m0, rx0), mn1 = fmaxf(m1, rx1);
        float corr0 = __expf(m0 - mn0), corr1 = __expf(m1 - mn1);
        m0 = mn0; m1 = mn1;
        float rs0 = 0.f, rs1 = 0.f;
        #pragma unroll
        for (int n0 = 0; n0 < 8; n0++) {
            float p0 = __expf(s[n0][0] - mn0);
            float p1 = __expf(s[n0][1] - mn0);
            float p2 = __expf(s[n0][2] - mn1);
            float p3 = __expf(s[n0][3] - mn1);
            rs0 += p0 + p1; rs1 += p2 + p3;
            o[n0][0] *= corr0; o[n0][1] *= corr0;
            o[n0][2] *= corr1; o[n0][3] *= corr1;
            *(float2*)&Ps[qrow * 68 + n0 * 8 + 2 * tig] =
                make_float2(__uint_as_float(f2tf(p0)), __uint_as_float(f2tf(p1)));
            *(float2*)&Ps[(qrow + 8) * 68 + n0 * 8 + 2 * tig] =
                make_float2(__uint_as_float(f2tf(p2)), __uint_as_float(f2tf(p3)));
        }
        rs0 += __shfl_xor_sync(0xffffffffu, rs0, 1);
        rs0 += __shfl_xor_sync(0xffffffffu, rs0, 2);
        rs1 += __shfl_xor_sync(0xffffffffu, rs1, 1);
        rs1 += __shfl_xor_sync(0xffffffffu, rs1, 2);
        l0 = l0 * corr0 + rs0;
        l1 = l1 * corr1 + rs1;
        __syncwarp();

        // ---- O[16x64] += P . V ----
        #pragma unroll
        for (int k0 = 0; k0 < 8; k0++) {
            unsigned ap[4];
            ap[0] = __float_as_uint(Ps[qrow * 68 + k0 * 8 + tig]);
            ap[1] = __float_as_uint(Ps[(qrow + 8) * 68 + k0 * 8 + tig]);
            ap[2] = __float_as_uint(Ps[qrow * 68 + k0 * 8 + tig + 4]);
            ap[3] = __float_as_uint(Ps[(qrow + 8) * 68 + k0 * 8 + tig + 4]);
            #pragma unroll
            for (int n0 = 0; n0 < 8; n0++) {
                unsigned b0 = __float_as_uint(Vs[(k0 * 8 + tig) * 72 + n0 * 8 + gid]);
                unsigned b1 = __float_as_uint(Vs[(k0 * 8 + tig + 4) * 72 + n0 * 8 + gid]);
                mma8(o[n0], ap, b0, b1);
            }
        }
        __syncthreads();
    }

    // ---- epilogue: normalize, write g_O ----
    const float inv0 = 1.0f / l0, inv1 = 1.0f / l1;
    const int bb = bh >> 2, h = bh & 3;
    const int r0 = qt * 128 + qrow;
    size_t base0 = (size_t)(bb * SEQ + r0) * DM + h * 64;
    size_t base1 = base0 + (size_t)8 * DM;
    #pragma unroll
    for (int n0 = 0; n0 < 8; n0++) {
        *(float2*)&g_O[base0 + n0 * 8 + 2 * tig] =
            make_float2(o[n0][0] * inv0, o[n0][1] * inv0);
        *(float2*)&g_O[base1 + n0 * 8 + 2 * tig] =
            make_float2(o[n0][2] * inv1, o[n0][3] * inv1);
    }
}

// =====================================================================
// Kernel 3: output projection — bf16-split mma.  d_out = g_O @ Wo + bo
// =====================================================================
__global__ __launch_bounds__(256) void out_kernel(const float* __restrict__ Wo,
                                                  const float* __restrict__ bo,
                                                  float* __restrict__ out)
{
    __shared__ unsigned short Ah[64 * 18], Al[64 * 18];
    __shared__ unsigned short Bh[64 * 18], Bl[64 * 18];
    const int m0 = blockIdx.x * 64;
    const int n0 = blockIdx.y * 64;
    const int tid  = threadIdx.x;
    const int w    = tid >> 5;
    const int lane = tid & 31;
    const int gid  = lane >> 2, tig = lane & 3;
    const int mrow = (w & 3) * 16;
    const int nc0  = (w >> 2) * 32;

    float acc[4][4] = {};
    for (int k0 = 0; k0 < DM; k0 += 16) {
        {
            int i = tid >> 2, c = tid & 3;
            float4 a = *(const float4*)&g_O[(size_t)(m0 + i) * DM + k0 + c * 4];
            float av[4] = {a.x, a.y, a.z, a.w};
            #pragma unroll
            for (int u = 0; u < 4; u++)
                bsplit(av[u], Ah[i * 18 + c * 4 + u], Al[i * 18 + c * 4 + u]);
            int kk = tid >> 4, c2 = tid & 15;
            float4 wv = *(const float4*)&Wo[(size_t)(k0 + kk) * DM + n0 + c2 * 4];
            float wf[4] = {wv.x, wv.y, wv.z, wv.w};
            #pragma unroll
            for (int u = 0; u < 4; u++)
                bsplit(wf[u], Bh[(c2 * 4 + u) * 18 + kk], Bl[(c2 * 4 + u) * 18 + kk]);
        }
        __syncthreads();
        unsigned ah[4], al[4];
        ah[0] = *(const unsigned*)&Ah[(mrow + gid)     * 18 + 2 * tig];
        ah[1] = *(const unsigned*)&Ah[(mrow + gid + 8) * 18 + 2 * tig];
        ah[2] = *(const unsigned*)&Ah[(mrow + gid)     * 18 + 8 + 2 * tig];
        ah[3] = *(const unsigned*)&Ah[(mrow + gid + 8) * 18 + 8 + 2 * tig];
        al[0] = *(const unsigned*)&Al[(mrow + gid)     * 18 + 2 * tig];
        al[1] = *(const unsigned*)&Al[(mrow + gid + 8) * 18 + 2 * tig];
        al[2] = *(const unsigned*)&Al[(mrow + gid)     * 18 + 8 + 2 * tig];
        al[3] = *(const unsigned*)&Al[(mrow + gid + 8) * 18 + 8 + 2 * tig];
        #pragma unroll
        for (int nt = 0; nt < 4; nt++) {
            int n = nc0 + nt * 8 + gid;
            unsigned bh0 = *(const unsigned*)&Bh[n * 18 + 2 * tig];
            unsigned bh1 = *(const unsigned*)&Bh[n * 18 + 8 + 2 * tig];
            unsigned bl0 = *(const unsigned*)&Bl[n * 18 + 2 * tig];
            unsigned bl1 = *(const unsigned*)&Bl[n * 18 + 8 + 2 * tig];
            mmabf(acc[nt], ah, bh0, bh1);
            mmabf(acc[nt], al, bh0, bh1);
            mmabf(acc[nt], ah, bl0, bl1);
        }
        __syncthreads();
    }

    const int r0 = m0 + mrow + gid;
    #pragma unroll
    for (int nt = 0; nt < 4; nt++) {
        int c0 = n0 + nc0 + nt * 8 + 2 * tig;
        *(float2*)&out[(size_t)r0 * DM + c0] =
            make_float2(acc[nt][0] + bo[c0], acc[nt][1] + bo[c0 + 1]);
        *(float2*)&out[(size_t)(r0 + 8) * DM + c0] =
            make_float2(acc[nt][2] + bo[c0], acc[nt][3] + bo[c0 + 1]);
    }
}

// =====================================================================
extern "C" void kernel_launch(void* const* d_in, const int* in_sizes, int n_in,
                              void* d_out, int out_size)
{
    const float* query = (const float*)d_in[0];
    const float* key_  = (const float*)d_in[1];
    const float* value = (const float*)d_in[2];
    const float* Wq    = (const float*)d_in[3];
    const float* bq    = (const float*)d_in[4];
    const float* Wk    = (const float*)d_in[5];
    const float* bk    = (const float*)d_in[6];
    const float* Wv    = (const float*)d_in[7];
    const float* bv    = (const float*)d_in[8];
    const float* W2    = (const float*)d_in[9];
    const float* alpha = (const float*)d_in[10];
    const float* Wo    = (const float*)d_in[11];
    const float* bo    = (const float*)d_in[12];
    float* out = (float*)d_out;

    cudaFuncSetAttribute(prep_kernel, cudaFuncAttributeMaxDynamicSharedMemorySize, PREP_SMEM);
    cudaFuncSetAttribute(attn_kernel, cudaFuncAttributeMaxDynamicSharedMemorySize, ATTN_SMEM);

    prep_kernel<<<NH, 256, PREP_SMEM>>>(W2, alpha, Wk, bk);
    proj_kernel<<<dim3(128, 4, 3), 256>>>(query, key_, value, Wq, bq, Wv, bv);
    attn_kernel<<<dim3(16, BHT), 256, ATTN_SMEM>>>();
    out_kernel<<<dim3(128, 4), 256>>>(Wo, bo, out);
}